// round 1
// baseline (speedup 1.0000x reference)
#include <cuda_runtime.h>
#include <math.h>

// Problem constants
#define BATCH 4
#define SEQ   2048
#define HID   2048
#define NHEAD 16
#define HD    128
#define MTOT  (BATCH*SEQ)        // 8192
#define SCALE 0.08838834764831845f   // 1/sqrt(128)

// Scratch buffers (device globals: allocation-free per harness rules)
__device__ float g_Q[(size_t)BATCH*NHEAD*SEQ*HD];   // [b*16+h][s][d]
__device__ float g_K[(size_t)BATCH*NHEAD*SEQ*HD];
__device__ float g_V[(size_t)BATCH*NHEAD*SEQ*HD];
__device__ float g_AO[(size_t)MTOT*HID];            // attention out, [B*S, H]

// ---------------------------------------------------------------------------
// GEMM (NT): C[m,n] = sum_k A[m,k] * W[n,k]
//   A: [M=8192, K=2048] row-major;  W: [N=2048, K=2048] row-major
//   qkv_mode=0: scatter C into [b, head, s, d] layout (for attention)
//   qkv_mode=1: plain row-major [M, N] (final output)
// ---------------------------------------------------------------------------
#define BM 128
#define BN 128
#define BKK 8

__global__ __launch_bounds__(256, 2)
void gemm_nt_kernel(const float* __restrict__ A, const float* __restrict__ W,
                    float* __restrict__ out, int qkv_mode)
{
    __shared__ float As[BKK][BM];
    __shared__ float Bs[BKK][BN];
    const int K = HID;
    const int m0 = blockIdx.y * BM;
    const int n0 = blockIdx.x * BN;
    const int tid = threadIdx.x;
    const int ty = tid >> 4;      // 0..15
    const int tx = tid & 15;      // 0..15

    float acc[8][8];
#pragma unroll
    for (int i = 0; i < 8; i++)
#pragma unroll
        for (int j = 0; j < 8; j++) acc[i][j] = 0.f;

    // Load mapping: each thread loads one float4 of A and one of W per k-tile.
    const int lm = tid >> 1;          // 0..127 (row within tile)
    const int lk = (tid & 1) << 2;    // 0 or 4
    const float* Aptr = A + (size_t)(m0 + lm) * K + lk;
    const float* Wptr = W + (size_t)(n0 + lm) * K + lk;

    for (int k0 = 0; k0 < K; k0 += BKK) {
        float4 av = *(const float4*)(Aptr + k0);
        float4 bv = *(const float4*)(Wptr + k0);
        As[lk+0][lm] = av.x; As[lk+1][lm] = av.y;
        As[lk+2][lm] = av.z; As[lk+3][lm] = av.w;
        Bs[lk+0][lm] = bv.x; Bs[lk+1][lm] = bv.y;
        Bs[lk+2][lm] = bv.z; Bs[lk+3][lm] = bv.w;
        __syncthreads();

#pragma unroll
        for (int k = 0; k < BKK; k++) {
            float4 a0 = *(const float4*)&As[k][ty*8];
            float4 a1 = *(const float4*)&As[k][ty*8 + 4];
            float4 b0 = *(const float4*)&Bs[k][tx*8];
            float4 b1 = *(const float4*)&Bs[k][tx*8 + 4];
            float a[8] = {a0.x,a0.y,a0.z,a0.w,a1.x,a1.y,a1.z,a1.w};
            float b[8] = {b0.x,b0.y,b0.z,b0.w,b1.x,b1.y,b1.z,b1.w};
#pragma unroll
            for (int i = 0; i < 8; i++)
#pragma unroll
                for (int j = 0; j < 8; j++)
                    acc[i][j] = fmaf(a[i], b[j], acc[i][j]);
        }
        __syncthreads();
    }

    // Epilogue
#pragma unroll
    for (int i = 0; i < 8; i++) {
        const int gm = m0 + ty*8 + i;
        const int gn = n0 + tx*8;      // 8 consecutive cols, same head (128-aligned groups)
        float4 v0 = make_float4(acc[i][0], acc[i][1], acc[i][2], acc[i][3]);
        float4 v1 = make_float4(acc[i][4], acc[i][5], acc[i][6], acc[i][7]);
        if (qkv_mode == 0) {
            const int b = gm >> 11;        // gm / SEQ
            const int s = gm & (SEQ-1);
            const int h = gn >> 7;         // gn / HD
            const int d = gn & (HD-1);
            float* dst = out + (((size_t)(b*NHEAD + h))*SEQ + s)*HD + d;
            *(float4*)dst       = v0;
            *(float4*)(dst + 4) = v1;
        } else {
            float* dst = out + (size_t)gm * HID + gn;
            *(float4*)dst       = v0;
            *(float4*)(dst + 4) = v1;
        }
    }
}

// ---------------------------------------------------------------------------
// RoPE — replicates the reference's swapped sin/cos naming:
//   c := sin(freqs), s := cos(freqs)
//   x1' = x1*c - x2*s = x1*sin - x2*cos
//   x2' = x1*s + x2*c = x1*cos + x2*sin
// Layout: [b*16+h][s][d], d split at 64.
// ---------------------------------------------------------------------------
__global__ void rope_kernel(float* __restrict__ Q, float* __restrict__ Kk)
{
    const int row = blockIdx.x * 4 + (threadIdx.x >> 6);   // 0..131071
    const int j   = threadIdx.x & 63;
    const int s   = row & (SEQ - 1);

    // inv_freq = 10000^(-(2j)/128), computed in double for accuracy
    const double e = -((double)(2*j) / 128.0) * 9.210340371976184;  // ln(10000)
    const float inv = (float)exp(e);
    const float ang = (float)s * inv;
    float sn, cs;
    sincosf(ang, &sn, &cs);    // accurate variant: args up to ~2047 rad

    const size_t base = (size_t)row * HD;
    float q1 = Q[base + j], q2 = Q[base + j + 64];
    Q[base + j]      = q1 * sn - q2 * cs;
    Q[base + j + 64] = q1 * cs + q2 * sn;

    float k1 = Kk[base + j], k2 = Kk[base + j + 64];
    Kk[base + j]      = k1 * sn - k2 * cs;
    Kk[base + j + 64] = k1 * cs + k2 * sn;
}

// ---------------------------------------------------------------------------
// Causal flash attention, fp32. Br=Bc=64, hd=128, 256 threads.
// Grid: (S/64 q-tiles, B*nh). Online softmax, O accumulators in registers.
// ---------------------------------------------------------------------------
#define BR 64
#define BC 64
#define HDP 129     // padded stride for sQ, sK rows (scalar access, 2-way max)
#define VP  132     // padded stride for sV rows (16B-aligned for float4)
#define BCP 65      // padded stride for score tile rows

#define ATTN_SMEM_FLOATS (BR*HDP + BC*HDP + BC*VP + BR*BCP + 3*BR)
#define ATTN_SMEM_BYTES  (ATTN_SMEM_FLOATS * 4)

__global__ __launch_bounds__(256, 1)
void attn_kernel(const float* __restrict__ Q, const float* __restrict__ K,
                 const float* __restrict__ V, float* __restrict__ out)
{
    extern __shared__ float smem[];
    float* sQ     = smem;                  // BR * HDP
    float* sK     = sQ + BR*HDP;           // BC * HDP
    float* sV     = sK + BC*HDP;           // BC * VP
    float* sS     = sV + BC*VP;            // BR * BCP
    float* sMax   = sS + BR*BCP;           // BR
    float* sSum   = sMax + BR;             // BR
    float* sAlpha = sSum + BR;             // BR

    const int bh = blockIdx.y;             // 0..63  (= b*16 + h)
    const int q0 = blockIdx.x * BR;
    const int tid = threadIdx.x;
    const int ty = tid >> 4;               // 0..15
    const int tx = tid & 15;               // 0..15
    const int r0 = ty * 4;                 // 4 owned rows
    const int c0o = tx * 8;                // 8 owned O columns

    const float* Qb = Q + (size_t)bh * SEQ * HD;
    const float* Kb = K + (size_t)bh * SEQ * HD;
    const float* Vb = V + (size_t)bh * SEQ * HD;

    // Load Q tile (64x128) once
    for (int i = tid; i < BR*HD/4; i += 256) {
        const int r = i >> 5;              // 32 float4 per row
        const int c4 = (i & 31) << 2;
        float4 v = *(const float4*)&Qb[(size_t)(q0 + r)*HD + c4];
        float* d = &sQ[r*HDP + c4];
        d[0] = v.x; d[1] = v.y; d[2] = v.z; d[3] = v.w;
    }
    if (tid < BR) { sMax[tid] = -1e30f; sSum[tid] = 0.f; }

    float o[4][8];
#pragma unroll
    for (int i = 0; i < 4; i++)
#pragma unroll
        for (int j = 0; j < 8; j++) o[i][j] = 0.f;

    const int ktmax = q0 / BC;             // diagonal tile index (causal)
    for (int kt = 0; kt <= ktmax; kt++) {
        const int k0 = kt * BC;
        __syncthreads();   // guard smem reuse vs previous iteration's reads

        // Load K and V tiles (64x128 each)
        for (int i = tid; i < BC*HD/4; i += 256) {
            const int r = i >> 5;
            const int c4 = (i & 31) << 2;
            float4 kv = *(const float4*)&Kb[(size_t)(k0 + r)*HD + c4];
            float* dk = &sK[r*HDP + c4];
            dk[0] = kv.x; dk[1] = kv.y; dk[2] = kv.z; dk[3] = kv.w;
            float4 vv = *(const float4*)&Vb[(size_t)(k0 + r)*HD + c4];
            *(float4*)&sV[r*VP + c4] = vv;
        }
        __syncthreads();

        // Phase A: S = Q*K^T (each thread: 4 rows x 4 cols)
        float sacc[4][4];
#pragma unroll
        for (int i = 0; i < 4; i++)
#pragma unroll
            for (int j = 0; j < 4; j++) sacc[i][j] = 0.f;
#pragma unroll 8
        for (int k = 0; k < HD; k++) {
            float a[4], b[4];
#pragma unroll
            for (int i = 0; i < 4; i++) a[i] = sQ[(r0 + i)*HDP + k];
#pragma unroll
            for (int j = 0; j < 4; j++) b[j] = sK[(tx*4 + j)*HDP + k];
#pragma unroll
            for (int i = 0; i < 4; i++)
#pragma unroll
                for (int j = 0; j < 4; j++)
                    sacc[i][j] = fmaf(a[i], b[j], sacc[i][j]);
        }
        // scale + causal mask, write score tile
#pragma unroll
        for (int i = 0; i < 4; i++) {
            const int qi = q0 + r0 + i;
#pragma unroll
            for (int j = 0; j < 4; j++) {
                const int ki = k0 + tx*4 + j;
                float v = sacc[i][j] * SCALE;
                if (ki > qi) v = -1e30f;
                sS[(r0 + i)*BCP + tx*4 + j] = v;
            }
        }
        __syncthreads();

        // Phase B: online softmax update (one thread per row)
        if (tid < BR) {
            const int r = tid;
            float mold = sMax[r];
            float mx = mold;
            for (int c = 0; c < BC; c++) mx = fmaxf(mx, sS[r*BCP + c]);
            const float alpha = __expf(mold - mx);
            float sum = sSum[r] * alpha;
            for (int c = 0; c < BC; c++) {
                float p = __expf(sS[r*BCP + c] - mx);
                sS[r*BCP + c] = p;
                sum += p;
            }
            sMax[r] = mx; sSum[r] = sum; sAlpha[r] = alpha;
        }
        __syncthreads();

        // Phase C: O = O*alpha + P*V
        float al[4];
#pragma unroll
        for (int i = 0; i < 4; i++) al[i] = sAlpha[r0 + i];
#pragma unroll
        for (int i = 0; i < 4; i++)
#pragma unroll
            for (int j = 0; j < 8; j++) o[i][j] *= al[i];

#pragma unroll 4
        for (int kk = 0; kk < BC; kk++) {
            float p[4];
#pragma unroll
            for (int i = 0; i < 4; i++) p[i] = sS[(r0 + i)*BCP + kk];
            float4 v0 = *(const float4*)&sV[kk*VP + c0o];
            float4 v1 = *(const float4*)&sV[kk*VP + c0o + 4];
            float vv[8] = {v0.x,v0.y,v0.z,v0.w,v1.x,v1.y,v1.z,v1.w};
#pragma unroll
            for (int i = 0; i < 4; i++)
#pragma unroll
                for (int j = 0; j < 8; j++)
                    o[i][j] = fmaf(p[i], vv[j], o[i][j]);
        }
    }

    // Epilogue: normalize + write to [B*S, H] layout for the O-projection GEMM
    const int b = bh >> 4;
    const int h = bh & 15;
#pragma unroll
    for (int i = 0; i < 4; i++) {
        const float inv = 1.f / sSum[r0 + i];
        const int srow = q0 + r0 + i;
        float* dst = out + ((size_t)(b*SEQ + srow))*HID + h*HD + c0o;
        float4 v0 = make_float4(o[i][0]*inv, o[i][1]*inv, o[i][2]*inv, o[i][3]*inv);
        float4 v1 = make_float4(o[i][4]*inv, o[i][5]*inv, o[i][6]*inv, o[i][7]*inv);
        *(float4*)dst       = v0;
        *(float4*)(dst + 4) = v1;
    }
}

// ---------------------------------------------------------------------------
// Launch
// ---------------------------------------------------------------------------
extern "C" void kernel_launch(void* const* d_in, const int* in_sizes, int n_in,
                              void* d_out, int out_size)
{
    const float* x  = (const float*)d_in[0];
    const float* Wq = (const float*)d_in[1];
    const float* Wk = (const float*)d_in[2];
    const float* Wv = (const float*)d_in[3];
    const float* Wo = (const float*)d_in[4];

    float *pQ, *pK, *pV, *pAO;
    cudaGetSymbolAddress((void**)&pQ,  g_Q);
    cudaGetSymbolAddress((void**)&pK,  g_K);
    cudaGetSymbolAddress((void**)&pV,  g_V);
    cudaGetSymbolAddress((void**)&pAO, g_AO);

    dim3 gemm_grid(HID / BN, MTOT / BM);   // (16, 64)

    gemm_nt_kernel<<<gemm_grid, 256>>>(x, Wq, pQ, 0);
    gemm_nt_kernel<<<gemm_grid, 256>>>(x, Wk, pK, 0);
    gemm_nt_kernel<<<gemm_grid, 256>>>(x, Wv, pV, 0);

    rope_kernel<<<BATCH*NHEAD*SEQ/4, 256>>>(pQ, pK);

    cudaFuncSetAttribute(attn_kernel, cudaFuncAttributeMaxDynamicSharedMemorySize,
                         ATTN_SMEM_BYTES);
    attn_kernel<<<dim3(SEQ/BR, BATCH*NHEAD), 256, ATTN_SMEM_BYTES>>>(pQ, pK, pV, pAO);

    gemm_nt_kernel<<<gemm_grid, 256>>>(pAO, Wo, (float*)d_out, 1);
}

// round 2
// speedup vs baseline: 1.5166x; 1.5166x over previous
#include <cuda_runtime.h>
#include <math.h>

// Problem constants
#define BATCH 4
#define SEQ   2048
#define HID   2048
#define NHEAD 16
#define HD    128
#define MTOT  (BATCH*SEQ)        // 8192
#define SCALE 0.08838834764831845f   // 1/sqrt(128)

// Scratch buffers
__device__ float g_Q[(size_t)BATCH*NHEAD*SEQ*HD];   // [b*16+h][s][d]
__device__ float g_K[(size_t)BATCH*NHEAD*SEQ*HD];
__device__ float g_V[(size_t)BATCH*NHEAD*SEQ*HD];
__device__ float g_AO[(size_t)MTOT*HID];            // attention out, [B*S, H]

// ---------------------------------------------------------------------------
// fp32 GEMM (NT): used for Q and K projections (precision-critical path).
// ---------------------------------------------------------------------------
#define BM 128
#define BN 128
#define BKK 8

__global__ __launch_bounds__(256, 2)
void gemm_nt_kernel(const float* __restrict__ A, const float* __restrict__ W,
                    float* __restrict__ out, int qkv_mode)
{
    __shared__ float As[BKK][BM];
    __shared__ float Bs[BKK][BN];
    const int K = HID;
    const int m0 = blockIdx.y * BM;
    const int n0 = blockIdx.x * BN;
    const int tid = threadIdx.x;
    const int ty = tid >> 4;
    const int tx = tid & 15;

    float acc[8][8];
#pragma unroll
    for (int i = 0; i < 8; i++)
#pragma unroll
        for (int j = 0; j < 8; j++) acc[i][j] = 0.f;

    const int lm = tid >> 1;
    const int lk = (tid & 1) << 2;
    const float* Aptr = A + (size_t)(m0 + lm) * K + lk;
    const float* Wptr = W + (size_t)(n0 + lm) * K + lk;

    for (int k0 = 0; k0 < K; k0 += BKK) {
        float4 av = *(const float4*)(Aptr + k0);
        float4 bv = *(const float4*)(Wptr + k0);
        As[lk+0][lm] = av.x; As[lk+1][lm] = av.y;
        As[lk+2][lm] = av.z; As[lk+3][lm] = av.w;
        Bs[lk+0][lm] = bv.x; Bs[lk+1][lm] = bv.y;
        Bs[lk+2][lm] = bv.z; Bs[lk+3][lm] = bv.w;
        __syncthreads();

#pragma unroll
        for (int k = 0; k < BKK; k++) {
            float4 a0 = *(const float4*)&As[k][ty*8];
            float4 a1 = *(const float4*)&As[k][ty*8 + 4];
            float4 b0 = *(const float4*)&Bs[k][tx*8];
            float4 b1 = *(const float4*)&Bs[k][tx*8 + 4];
            float a[8] = {a0.x,a0.y,a0.z,a0.w,a1.x,a1.y,a1.z,a1.w};
            float b[8] = {b0.x,b0.y,b0.z,b0.w,b1.x,b1.y,b1.z,b1.w};
#pragma unroll
            for (int i = 0; i < 8; i++)
#pragma unroll
                for (int j = 0; j < 8; j++)
                    acc[i][j] = fmaf(a[i], b[j], acc[i][j]);
        }
        __syncthreads();
    }

#pragma unroll
    for (int i = 0; i < 8; i++) {
        const int gm = m0 + ty*8 + i;
        const int gn = n0 + tx*8;
        float4 v0 = make_float4(acc[i][0], acc[i][1], acc[i][2], acc[i][3]);
        float4 v1 = make_float4(acc[i][4], acc[i][5], acc[i][6], acc[i][7]);
        if (qkv_mode == 0) {
            const int b = gm >> 11;
            const int s = gm & (SEQ-1);
            const int h = gn >> 7;
            const int d = gn & (HD-1);
            float* dst = out + (((size_t)(b*NHEAD + h))*SEQ + s)*HD + d;
            *(float4*)dst       = v0;
            *(float4*)(dst + 4) = v1;
        } else {
            float* dst = out + (size_t)gm * HID + gn;
            *(float4*)dst       = v0;
            *(float4*)(dst + 4) = v1;
        }
    }
}

// ---------------------------------------------------------------------------
// tf32 tensor-core GEMM (NT): used for V and O projections.
// C[m,n] = sum_k A[m,k]*W[n,k]; inputs rounded to tf32 (RN) on the smem fill.
// BM=BN=128, BK=32, 8 warps (2x4), warp tile 64x32, mma m16n8k8.
// Smem pad 36 -> fragment LDS fully bank-conflict-free.
// ---------------------------------------------------------------------------
#define TBM 128
#define TBN 128
#define TBK 32
#define TBKP 36

__device__ __forceinline__ float ftf32(float x) {
    unsigned u = __float_as_uint(x), r;
    asm("cvt.rna.tf32.f32 %0, %1;" : "=r"(r) : "r"(u));
    return __uint_as_float(r);
}

__device__ __forceinline__ void mma_tf32(float (&d)[4],
                                         const unsigned (&a)[4],
                                         const unsigned (&b)[2]) {
    asm volatile(
        "mma.sync.aligned.m16n8k8.row.col.f32.tf32.tf32.f32 "
        "{%0,%1,%2,%3}, {%4,%5,%6,%7}, {%8,%9}, {%0,%1,%2,%3};\n"
        : "+f"(d[0]), "+f"(d[1]), "+f"(d[2]), "+f"(d[3])
        : "r"(a[0]), "r"(a[1]), "r"(a[2]), "r"(a[3]),
          "r"(b[0]), "r"(b[1]));
}

__global__ __launch_bounds__(256)
void gemm_tf32_kernel(const float* __restrict__ A, const float* __restrict__ W,
                      float* __restrict__ out, int qkv_mode)
{
    __shared__ float As[TBM*TBKP];   // [m][k] pad 36
    __shared__ float Bs[TBN*TBKP];   // [n][k] pad 36

    const int K = HID;
    const int tid = threadIdx.x;
    const int m0 = blockIdx.y * TBM;
    const int n0 = blockIdx.x * TBN;
    const int warp = tid >> 5, lane = tid & 31;
    const int wm = (warp >> 2) * 64;       // warp row base within tile
    const int wn = (warp & 3) * 32;        // warp col base within tile
    const int g = lane >> 2, c = lane & 3;

    float acc[4][4][4];
#pragma unroll
    for (int mt = 0; mt < 4; mt++)
#pragma unroll
        for (int nt = 0; nt < 4; nt++)
#pragma unroll
            for (int e = 0; e < 4; e++) acc[mt][nt][e] = 0.f;

    // global->reg fetch mapping: 4 passes of (row = tid>>3 + 32p, k4 = (tid&7)*4)
    const int lr = tid >> 3;
    const int lk4 = (tid & 7) << 2;
    const float* Ab = A + (size_t)m0 * K;
    const float* Wb = W + (size_t)n0 * K;

    float4 pa[4], pb[4];
#pragma unroll
    for (int p = 0; p < 4; p++) {
        pa[p] = *(const float4*)(Ab + (size_t)(lr + 32*p) * K + lk4);
        pb[p] = *(const float4*)(Wb + (size_t)(lr + 32*p) * K + lk4);
    }

    const unsigned* Asu = (const unsigned*)As;
    const unsigned* Bsu = (const unsigned*)Bs;

    for (int kt = 0; kt < K / TBK; kt++) {
        // store prefetched regs -> smem (round to tf32)
#pragma unroll
        for (int p = 0; p < 4; p++) {
            float4 v = pa[p];
            v.x = ftf32(v.x); v.y = ftf32(v.y); v.z = ftf32(v.z); v.w = ftf32(v.w);
            *(float4*)&As[(lr + 32*p)*TBKP + lk4] = v;
            float4 w = pb[p];
            w.x = ftf32(w.x); w.y = ftf32(w.y); w.z = ftf32(w.z); w.w = ftf32(w.w);
            *(float4*)&Bs[(lr + 32*p)*TBKP + lk4] = w;
        }
        __syncthreads();

        // issue next tile's global loads (overlap with compute)
        if (kt + 1 < K / TBK) {
            const int k0 = (kt + 1) * TBK;
#pragma unroll
            for (int p = 0; p < 4; p++) {
                pa[p] = *(const float4*)(Ab + (size_t)(lr + 32*p) * K + k0 + lk4);
                pb[p] = *(const float4*)(Wb + (size_t)(lr + 32*p) * K + k0 + lk4);
            }
        }

        // compute: 4 k8-steps
#pragma unroll
        for (int k8 = 0; k8 < 4; k8++) {
            const int kb = k8 * 8;
            unsigned bf[4][2];
#pragma unroll
            for (int nt = 0; nt < 4; nt++) {
                const int n = wn + nt*8 + g;
                bf[nt][0] = Bsu[n*TBKP + kb + c];
                bf[nt][1] = Bsu[n*TBKP + kb + c + 4];
            }
#pragma unroll
            for (int mt = 0; mt < 4; mt++) {
                const int m = wm + mt*16;
                unsigned af[4];
                af[0] = Asu[(m + g)*TBKP + kb + c];
                af[1] = Asu[(m + g + 8)*TBKP + kb + c];
                af[2] = Asu[(m + g)*TBKP + kb + c + 4];
                af[3] = Asu[(m + g + 8)*TBKP + kb + c + 4];
#pragma unroll
                for (int nt = 0; nt < 4; nt++)
                    mma_tf32(acc[mt][nt], af, bf[nt]);
            }
        }
        __syncthreads();
    }

    // Epilogue
#pragma unroll
    for (int mt = 0; mt < 4; mt++) {
#pragma unroll
        for (int nt = 0; nt < 4; nt++) {
            const int row = m0 + wm + mt*16 + g;
            const int col = n0 + wn + nt*8 + 2*c;
            float2 lo = make_float2(acc[mt][nt][0], acc[mt][nt][1]);
            float2 hi = make_float2(acc[mt][nt][2], acc[mt][nt][3]);
            if (qkv_mode == 0) {
                const int b = row >> 11;
                const int s = row & (SEQ-1);
                const int h = col >> 7;
                const int d = col & (HD-1);
                float* dst = out + (((size_t)(b*NHEAD + h))*SEQ + s)*HD + d;
                *(float2*)dst = lo;
                *(float2*)(out + (((size_t)(b*NHEAD + h))*SEQ + (s)) * HD + d
                           + (size_t)8*HD) = hi;   // row+8 -> s+8 same b,h
            } else {
                *(float2*)(out + (size_t)row * HID + col) = lo;
                *(float2*)(out + (size_t)(row + 8) * HID + col) = hi;
            }
        }
    }
}

// ---------------------------------------------------------------------------
// RoPE (swapped sin/cos naming, faithful to reference)
// ---------------------------------------------------------------------------
__global__ void rope_kernel(float* __restrict__ Q, float* __restrict__ Kk)
{
    const int row = blockIdx.x * 4 + (threadIdx.x >> 6);
    const int j   = threadIdx.x & 63;
    const int s   = row & (SEQ - 1);

    const double e = -((double)(2*j) / 128.0) * 9.210340371976184;
    const float inv = (float)exp(e);
    const float ang = (float)s * inv;
    float sn, cs;
    sincosf(ang, &sn, &cs);

    const size_t base = (size_t)row * HD;
    float q1 = Q[base + j], q2 = Q[base + j + 64];
    Q[base + j]      = q1 * sn - q2 * cs;
    Q[base + j + 64] = q1 * cs + q2 * sn;

    float k1 = Kk[base + j], k2 = Kk[base + j + 64];
    Kk[base + j]      = k1 * sn - k2 * cs;
    Kk[base + j + 64] = k1 * cs + k2 * sn;
}

// ---------------------------------------------------------------------------
// Causal flash attention, fp32, Br=Bc=64, 256 threads.
// Register online-softmax (shfl row reductions), float4 smem access.
// Thread (ty,tx): QK owns rows 4ty..+3, cols tx+16j (j<4);
//                 PV owns same rows,   cols 4tx+64j (j<2).
// ---------------------------------------------------------------------------
#define BR 64
#define BC 64
#define HDP 132
#define VP  132
#define BCP 68

#define ATTN_SMEM_FLOATS (BR*HDP + BC*HDP + BC*VP + BR*BCP)
#define ATTN_SMEM_BYTES  (ATTN_SMEM_FLOATS * 4)

__global__ __launch_bounds__(256, 1)
void attn_kernel(const float* __restrict__ Q, const float* __restrict__ K,
                 const float* __restrict__ V, float* __restrict__ out)
{
    extern __shared__ float smem[];
    float* sQ = smem;                // BR * HDP
    float* sK = sQ + BR*HDP;         // BC * HDP
    float* sV = sK + BC*HDP;         // BC * VP
    float* sS = sV + BC*VP;          // BR * BCP

    const int bh = blockIdx.y;
    const int q0 = blockIdx.x * BR;
    const int tid = threadIdx.x;
    const int ty = tid >> 4;
    const int tx = tid & 15;
    const int r0 = ty * 4;

    const float* Qb = Q + (size_t)bh * SEQ * HD;
    const float* Kb = K + (size_t)bh * SEQ * HD;
    const float* Vb = V + (size_t)bh * SEQ * HD;

    // Load Q tile (64x128)
    for (int i = tid; i < BR*HD/4; i += 256) {
        const int r = i >> 5;
        const int c4 = (i & 31) << 2;
        *(float4*)&sQ[r*HDP + c4] = *(const float4*)&Qb[(size_t)(q0 + r)*HD + c4];
    }

    float m_i[4], l_i[4], o[4][2][4];
#pragma unroll
    for (int i = 0; i < 4; i++) {
        m_i[i] = -1e30f; l_i[i] = 0.f;
#pragma unroll
        for (int j = 0; j < 2; j++)
#pragma unroll
            for (int e = 0; e < 4; e++) o[i][j][e] = 0.f;
    }

    const int ktmax = q0 / BC;
    for (int kt = 0; kt <= ktmax; kt++) {
        const int k0 = kt * BC;
        __syncthreads();   // protect sK/sV/sS reuse

        for (int i = tid; i < BC*HD/4; i += 256) {
            const int r = i >> 5;
            const int c4 = (i & 31) << 2;
            *(float4*)&sK[r*HDP + c4] = *(const float4*)&Kb[(size_t)(k0 + r)*HD + c4];
            *(float4*)&sV[r*VP  + c4] = *(const float4*)&Vb[(size_t)(k0 + r)*HD + c4];
        }
        __syncthreads();

        // QK: scores p[i][j], cols tx+16j
        float p[4][4];
#pragma unroll
        for (int i = 0; i < 4; i++)
#pragma unroll
            for (int j = 0; j < 4; j++) p[i][j] = 0.f;

#pragma unroll 4
        for (int k = 0; k < HD; k += 4) {
            float4 qv[4], kv[4];
#pragma unroll
            for (int i = 0; i < 4; i++) qv[i] = *(const float4*)&sQ[(r0+i)*HDP + k];
#pragma unroll
            for (int j = 0; j < 4; j++) kv[j] = *(const float4*)&sK[(tx+16*j)*HDP + k];
#pragma unroll
            for (int i = 0; i < 4; i++)
#pragma unroll
                for (int j = 0; j < 4; j++) {
                    p[i][j] = fmaf(qv[i].x, kv[j].x, p[i][j]);
                    p[i][j] = fmaf(qv[i].y, kv[j].y, p[i][j]);
                    p[i][j] = fmaf(qv[i].z, kv[j].z, p[i][j]);
                    p[i][j] = fmaf(qv[i].w, kv[j].w, p[i][j]);
                }
        }

        // Register online softmax (row group = 16 lanes, shfl.bfly)
#pragma unroll
        for (int i = 0; i < 4; i++) {
            const int qi = q0 + r0 + i;
            float mx = m_i[i];
#pragma unroll
            for (int j = 0; j < 4; j++) {
                const int ki = k0 + tx + 16*j;
                float v = (ki <= qi) ? p[i][j] * SCALE : -1e30f;
                p[i][j] = v;
                mx = fmaxf(mx, v);
            }
#pragma unroll
            for (int off = 8; off > 0; off >>= 1)
                mx = fmaxf(mx, __shfl_xor_sync(0xffffffffu, mx, off));
            const float alpha = __expf(m_i[i] - mx);
            m_i[i] = mx;
            float ls = 0.f;
#pragma unroll
            for (int j = 0; j < 4; j++) {
                float e = __expf(p[i][j] - mx);
                p[i][j] = e;
                ls += e;
            }
#pragma unroll
            for (int off = 8; off > 0; off >>= 1)
                ls += __shfl_xor_sync(0xffffffffu, ls, off);
            l_i[i] = l_i[i] * alpha + ls;
#pragma unroll
            for (int j = 0; j < 2; j++)
#pragma unroll
                for (int e = 0; e < 4; e++) o[i][j][e] *= alpha;
#pragma unroll
            for (int j = 0; j < 4; j++) sS[(r0+i)*BCP + tx + 16*j] = p[i][j];
        }
        __syncthreads();

        // PV: O[r0+i][4tx+64j] += sum_k p * V
#pragma unroll 2
        for (int kk = 0; kk < BC; kk += 4) {
            float pr[4][4];
#pragma unroll
            for (int i = 0; i < 4; i++)
                *(float4*)&pr[i][0] = *(const float4*)&sS[(r0+i)*BCP + kk];
#pragma unroll
            for (int kq = 0; kq < 4; kq++) {
                float4 v0 = *(const float4*)&sV[(kk+kq)*VP + 4*tx];
                float4 v1 = *(const float4*)&sV[(kk+kq)*VP + 4*tx + 64];
#pragma unroll
                for (int i = 0; i < 4; i++) {
                    const float pi = pr[i][kq];
                    o[i][0][0] = fmaf(pi, v0.x, o[i][0][0]);
                    o[i][0][1] = fmaf(pi, v0.y, o[i][0][1]);
                    o[i][0][2] = fmaf(pi, v0.z, o[i][0][2]);
                    o[i][0][3] = fmaf(pi, v0.w, o[i][0][3]);
                    o[i][1][0] = fmaf(pi, v1.x, o[i][1][0]);
                    o[i][1][1] = fmaf(pi, v1.y, o[i][1][1]);
                    o[i][1][2] = fmaf(pi, v1.z, o[i][1][2]);
                    o[i][1][3] = fmaf(pi, v1.w, o[i][1][3]);
                }
            }
        }
    }

    // Epilogue: normalize + write [B*S, H] for O-projection
    const int b = bh >> 4;
    const int h = bh & 15;
#pragma unroll
    for (int i = 0; i < 4; i++) {
        const float inv = 1.f / l_i[i];
        const int srow = q0 + r0 + i;
        float* dst = out + ((size_t)(b*SEQ + srow))*HID + h*HD;
        float4 w0 = make_float4(o[i][0][0]*inv, o[i][0][1]*inv, o[i][0][2]*inv, o[i][0][3]*inv);
        float4 w1 = make_float4(o[i][1][0]*inv, o[i][1][1]*inv, o[i][1][2]*inv, o[i][1][3]*inv);
        *(float4*)(dst + 4*tx)      = w0;
        *(float4*)(dst + 4*tx + 64) = w1;
    }
}

// ---------------------------------------------------------------------------
// Launch
// ---------------------------------------------------------------------------
extern "C" void kernel_launch(void* const* d_in, const int* in_sizes, int n_in,
                              void* d_out, int out_size)
{
    const float* x  = (const float*)d_in[0];
    const float* Wq = (const float*)d_in[1];
    const float* Wk = (const float*)d_in[2];
    const float* Wv = (const float*)d_in[3];
    const float* Wo = (const float*)d_in[4];

    float *pQ, *pK, *pV, *pAO;
    cudaGetSymbolAddress((void**)&pQ,  g_Q);
    cudaGetSymbolAddress((void**)&pK,  g_K);
    cudaGetSymbolAddress((void**)&pV,  g_V);
    cudaGetSymbolAddress((void**)&pAO, g_AO);

    dim3 gemm_grid(HID / BN, MTOT / BM);   // (16, 64)

    gemm_nt_kernel<<<gemm_grid, 256>>>(x, Wq, pQ, 0);     // fp32 (logit path)
    gemm_nt_kernel<<<gemm_grid, 256>>>(x, Wk, pK, 0);     // fp32 (logit path)
    gemm_tf32_kernel<<<gemm_grid, 256>>>(x, Wv, pV, 0);   // tf32 tensor core

    rope_kernel<<<BATCH*NHEAD*SEQ/4, 256>>>(pQ, pK);

    cudaFuncSetAttribute(attn_kernel, cudaFuncAttributeMaxDynamicSharedMemorySize,
                         ATTN_SMEM_BYTES);
    attn_kernel<<<dim3(SEQ/BR, BATCH*NHEAD), 256, ATTN_SMEM_BYTES>>>(pQ, pK, pV, pAO);

    gemm_tf32_kernel<<<gemm_grid, 256>>>(pAO, Wo, (float*)d_out, 1);  // tf32
}

// round 3
// speedup vs baseline: 4.1510x; 2.7371x over previous
#include <cuda_runtime.h>
#include <math.h>

// Problem constants
#define BATCH 4
#define SEQ   2048
#define HID   2048
#define NHEAD 16
#define HD    128
#define MTOT  (BATCH*SEQ)        // 8192
#define SCALE 0.08838834764831845f   // 1/sqrt(128)

// Scratch buffers
__device__ float g_Q[(size_t)BATCH*NHEAD*SEQ*HD];   // [b*16+h][s][d]
__device__ float g_K[(size_t)BATCH*NHEAD*SEQ*HD];
__device__ float g_V[(size_t)BATCH*NHEAD*SEQ*HD];
__device__ float g_AO[(size_t)MTOT*HID];            // attention out, [B*S, H]

// ---------------------------------------------------------------------------
// tf32 helpers
// ---------------------------------------------------------------------------
__device__ __forceinline__ float ftf32(float x) {
    unsigned u = __float_as_uint(x), r;
    asm("cvt.rna.tf32.f32 %0, %1;" : "=r"(r) : "r"(u));
    return __uint_as_float(r);
}

__device__ __forceinline__ void mma_tf32(float (&d)[4],
                                         const unsigned (&a)[4],
                                         const unsigned (&b)[2]) {
    asm volatile(
        "mma.sync.aligned.m16n8k8.row.col.f32.tf32.tf32.f32 "
        "{%0,%1,%2,%3}, {%4,%5,%6,%7}, {%8,%9}, {%0,%1,%2,%3};\n"
        : "+f"(d[0]), "+f"(d[1]), "+f"(d[2]), "+f"(d[3])
        : "r"(a[0]), "r"(a[1]), "r"(a[2]), "r"(a[3]),
          "r"(b[0]), "r"(b[1]));
}

// ---------------------------------------------------------------------------
// tf32 tensor-core GEMM (NT): all projections.
// C[m,n] = sum_k A[m,k]*W[n,k]; inputs rounded to tf32 (RN) on the smem fill.
// BM=BN=128, BK=32, 8 warps (2x4), warp tile 64x32, mma m16n8k8.
// ---------------------------------------------------------------------------
#define TBM 128
#define TBN 128
#define TBK 32
#define TBKP 36

__global__ __launch_bounds__(256)
void gemm_tf32_kernel(const float* __restrict__ A, const float* __restrict__ W,
                      float* __restrict__ out, int qkv_mode)
{
    __shared__ float As[TBM*TBKP];   // [m][k] pad 36
    __shared__ float Bs[TBN*TBKP];   // [n][k] pad 36

    const int K = HID;
    const int tid = threadIdx.x;
    const int m0 = blockIdx.y * TBM;
    const int n0 = blockIdx.x * TBN;
    const int warp = tid >> 5, lane = tid & 31;
    const int wm = (warp >> 2) * 64;
    const int wn = (warp & 3) * 32;
    const int g = lane >> 2, c = lane & 3;

    float acc[4][4][4];
#pragma unroll
    for (int mt = 0; mt < 4; mt++)
#pragma unroll
        for (int nt = 0; nt < 4; nt++)
#pragma unroll
            for (int e = 0; e < 4; e++) acc[mt][nt][e] = 0.f;

    const int lr = tid >> 3;
    const int lk4 = (tid & 7) << 2;
    const float* Ab = A + (size_t)m0 * K;
    const float* Wb = W + (size_t)n0 * K;

    float4 pa[4], pb[4];
#pragma unroll
    for (int p = 0; p < 4; p++) {
        pa[p] = *(const float4*)(Ab + (size_t)(lr + 32*p) * K + lk4);
        pb[p] = *(const float4*)(Wb + (size_t)(lr + 32*p) * K + lk4);
    }

    const unsigned* Asu = (const unsigned*)As;
    const unsigned* Bsu = (const unsigned*)Bs;

    for (int kt = 0; kt < K / TBK; kt++) {
#pragma unroll
        for (int p = 0; p < 4; p++) {
            float4 v = pa[p];
            v.x = ftf32(v.x); v.y = ftf32(v.y); v.z = ftf32(v.z); v.w = ftf32(v.w);
            *(float4*)&As[(lr + 32*p)*TBKP + lk4] = v;
            float4 w = pb[p];
            w.x = ftf32(w.x); w.y = ftf32(w.y); w.z = ftf32(w.z); w.w = ftf32(w.w);
            *(float4*)&Bs[(lr + 32*p)*TBKP + lk4] = w;
        }
        __syncthreads();

        if (kt + 1 < K / TBK) {
            const int k0 = (kt + 1) * TBK;
#pragma unroll
            for (int p = 0; p < 4; p++) {
                pa[p] = *(const float4*)(Ab + (size_t)(lr + 32*p) * K + k0 + lk4);
                pb[p] = *(const float4*)(Wb + (size_t)(lr + 32*p) * K + k0 + lk4);
            }
        }

#pragma unroll
        for (int k8 = 0; k8 < 4; k8++) {
            const int kb = k8 * 8;
            unsigned bf[4][2];
#pragma unroll
            for (int nt = 0; nt < 4; nt++) {
                const int n = wn + nt*8 + g;
                bf[nt][0] = Bsu[n*TBKP + kb + c];
                bf[nt][1] = Bsu[n*TBKP + kb + c + 4];
            }
#pragma unroll
            for (int mt = 0; mt < 4; mt++) {
                const int m = wm + mt*16;
                unsigned af[4];
                af[0] = Asu[(m + g)*TBKP + kb + c];
                af[1] = Asu[(m + g + 8)*TBKP + kb + c];
                af[2] = Asu[(m + g)*TBKP + kb + c + 4];
                af[3] = Asu[(m + g + 8)*TBKP + kb + c + 4];
#pragma unroll
                for (int nt = 0; nt < 4; nt++)
                    mma_tf32(acc[mt][nt], af, bf[nt]);
            }
        }
        __syncthreads();
    }

#pragma unroll
    for (int mt = 0; mt < 4; mt++) {
#pragma unroll
        for (int nt = 0; nt < 4; nt++) {
            const int row = m0 + wm + mt*16 + g;
            const int col = n0 + wn + nt*8 + 2*c;
            float2 lo = make_float2(acc[mt][nt][0], acc[mt][nt][1]);
            float2 hi = make_float2(acc[mt][nt][2], acc[mt][nt][3]);
            if (qkv_mode == 0) {
                const int b = row >> 11;
                const int s = row & (SEQ-1);
                const int h = col >> 7;
                const int d = col & (HD-1);
                float* dst = out + (((size_t)(b*NHEAD + h))*SEQ + s)*HD + d;
                *(float2*)dst = lo;
                *(float2*)(dst + (size_t)8*HD) = hi;   // row+8 -> s+8, same b,h
            } else {
                *(float2*)(out + (size_t)row * HID + col) = lo;
                *(float2*)(out + (size_t)(row + 8) * HID + col) = hi;
            }
        }
    }
}

// ---------------------------------------------------------------------------
// RoPE (swapped sin/cos naming, faithful to reference)
// ---------------------------------------------------------------------------
__global__ void rope_kernel(float* __restrict__ Q, float* __restrict__ Kk)
{
    const int row = blockIdx.x * 4 + (threadIdx.x >> 6);
    const int j   = threadIdx.x & 63;
    const int s   = row & (SEQ - 1);

    const double e = -((double)(2*j) / 128.0) * 9.210340371976184;
    const float inv = (float)exp(e);
    const float ang = (float)s * inv;
    float sn, cs;
    sincosf(ang, &sn, &cs);

    const size_t base = (size_t)row * HD;
    float q1 = Q[base + j], q2 = Q[base + j + 64];
    Q[base + j]      = q1 * sn - q2 * cs;
    Q[base + j + 64] = q1 * cs + q2 * sn;

    float k1 = Kk[base + j], k2 = Kk[base + j + 64];
    Kk[base + j]      = k1 * sn - k2 * cs;
    Kk[base + j + 64] = k1 * cs + k2 * sn;
}

// ---------------------------------------------------------------------------
// Causal flash attention on tf32 mma.sync.
// BR=128 rows per CTA, BC=64 keys per tile, 256 threads = 8 warps.
// Warp w owns rows wm=16w..16w+15 (softmax warp-local).
// Strides: Q/K 132 (A/B frag LDS bank 4g+c, conflict-free),
//          V 136 (B frag bank 8c+g, conflict-free), P 68 (4g+c, conflict-free).
// ---------------------------------------------------------------------------
#define ABR 128
#define ABC 64
#define QP  132
#define KP  132
#define VPS 136
#define PP  68

#define ATTN_SMEM_FLOATS (ABR*QP + ABC*KP + ABC*VPS + ABR*PP)
#define ATTN_SMEM_BYTES  (ATTN_SMEM_FLOATS * 4)

__global__ __launch_bounds__(256, 1)
void attn_mma_kernel(const float* __restrict__ Q, const float* __restrict__ K,
                     const float* __restrict__ V, float* __restrict__ out)
{
    extern __shared__ float smem[];
    float* sQ = smem;                   // ABR * QP
    float* sK = sQ + ABR*QP;            // ABC * KP
    float* sV = sK + ABC*KP;            // ABC * VPS
    float* sP = sV + ABC*VPS;           // ABR * PP
    const unsigned* uQ = (const unsigned*)sQ;
    const unsigned* uK = (const unsigned*)sK;
    const unsigned* uV = (const unsigned*)sV;
    const unsigned* uP = (const unsigned*)sP;

    const int bh = blockIdx.y;
    const int q0 = blockIdx.x * ABR;
    const int tid = threadIdx.x;
    const int warp = tid >> 5, lane = tid & 31;
    const int g = lane >> 2, c = lane & 3;
    const int wm = warp * 16;

    const float* Qb = Q + (size_t)bh * SEQ * HD;
    const float* Kb = K + (size_t)bh * SEQ * HD;
    const float* Vb = V + (size_t)bh * SEQ * HD;

    // Load Q tile (128x128), rounded to tf32
    for (int i = tid; i < ABR*HD/4; i += 256) {
        const int r = i >> 5;
        const int c4 = (i & 31) << 2;
        float4 v = *(const float4*)&Qb[(size_t)(q0 + r)*HD + c4];
        v.x = ftf32(v.x); v.y = ftf32(v.y); v.z = ftf32(v.z); v.w = ftf32(v.w);
        *(float4*)&sQ[r*QP + c4] = v;
    }

    // Per-thread online-softmax stats for rows (wm+g) and (wm+g+8)
    float m_r[2] = { -1e30f, -1e30f };
    float l_r[2] = { 0.f, 0.f };
    float acco[16][4];
#pragma unroll
    for (int nt = 0; nt < 16; nt++)
#pragma unroll
        for (int e = 0; e < 4; e++) acco[nt][e] = 0.f;

    const int qi0 = q0 + wm + g;
    const int qi1 = qi0 + 8;
    const int ktmax = q0/ABC + 1;      // (q0 + ABR - 1)/ABC

    for (int kt = 0; kt <= ktmax; kt++) {
        const int k0 = kt * ABC;
        __syncthreads();   // previous tile's sK/sV reads done

        // Load K,V tiles (64x128 each), rounded to tf32
        for (int i = tid; i < ABC*HD/4; i += 256) {
            const int r = i >> 5;
            const int c4 = (i & 31) << 2;
            float4 kv = *(const float4*)&Kb[(size_t)(k0 + r)*HD + c4];
            kv.x = ftf32(kv.x); kv.y = ftf32(kv.y); kv.z = ftf32(kv.z); kv.w = ftf32(kv.w);
            *(float4*)&sK[r*KP + c4] = kv;
            float4 vv = *(const float4*)&Vb[(size_t)(k0 + r)*HD + c4];
            vv.x = ftf32(vv.x); vv.y = ftf32(vv.y); vv.z = ftf32(vv.z); vv.w = ftf32(vv.w);
            *(float4*)&sV[r*VPS + c4] = vv;
        }
        __syncthreads();

        // Causal: warp-tile fully masked? (all rows < k0)
        if (k0 > q0 + wm + 15) continue;

        // ---- S = Q K^T : warp tile 16x64, acc in 8 n-frags ----
        float accs[8][4];
#pragma unroll
        for (int nt = 0; nt < 8; nt++)
#pragma unroll
            for (int e = 0; e < 4; e++) accs[nt][e] = 0.f;

#pragma unroll
        for (int k8 = 0; k8 < 16; k8++) {
            const int kb = k8 * 8;
            unsigned a[4];
            a[0] = uQ[(wm + g    )*QP + kb + c    ];
            a[1] = uQ[(wm + g + 8)*QP + kb + c    ];
            a[2] = uQ[(wm + g    )*QP + kb + c + 4];
            a[3] = uQ[(wm + g + 8)*QP + kb + c + 4];
#pragma unroll
            for (int nt = 0; nt < 8; nt++) {
                unsigned b[2];
                b[0] = uK[(8*nt + g)*KP + kb + c    ];
                b[1] = uK[(8*nt + g)*KP + kb + c + 4];
                mma_tf32(accs[nt], a, b);
            }
        }

        // ---- scale + causal mask + row max ----
        float mx0 = m_r[0], mx1 = m_r[1];
#pragma unroll
        for (int nt = 0; nt < 8; nt++) {
            const int colb = k0 + 8*nt + 2*c;
            float v0 = accs[nt][0] * SCALE; if (colb     > qi0) v0 = -1e30f;
            float v1 = accs[nt][1] * SCALE; if (colb + 1 > qi0) v1 = -1e30f;
            float v2 = accs[nt][2] * SCALE; if (colb     > qi1) v2 = -1e30f;
            float v3 = accs[nt][3] * SCALE; if (colb + 1 > qi1) v3 = -1e30f;
            accs[nt][0] = v0; accs[nt][1] = v1; accs[nt][2] = v2; accs[nt][3] = v3;
            mx0 = fmaxf(mx0, fmaxf(v0, v1));
            mx1 = fmaxf(mx1, fmaxf(v2, v3));
        }
        mx0 = fmaxf(mx0, __shfl_xor_sync(0xffffffffu, mx0, 1));
        mx0 = fmaxf(mx0, __shfl_xor_sync(0xffffffffu, mx0, 2));
        mx1 = fmaxf(mx1, __shfl_xor_sync(0xffffffffu, mx1, 1));
        mx1 = fmaxf(mx1, __shfl_xor_sync(0xffffffffu, mx1, 2));

        const float alpha0 = __expf(m_r[0] - mx0);
        const float alpha1 = __expf(m_r[1] - mx1);
        m_r[0] = mx0; m_r[1] = mx1;

        // ---- exp (round p to tf32; l sums the rounded p) ----
        float ls0 = 0.f, ls1 = 0.f;
#pragma unroll
        for (int nt = 0; nt < 8; nt++) {
            float p0 = ftf32(__expf(accs[nt][0] - mx0));
            float p1 = ftf32(__expf(accs[nt][1] - mx0));
            float p2 = ftf32(__expf(accs[nt][2] - mx1));
            float p3 = ftf32(__expf(accs[nt][3] - mx1));
            ls0 += p0 + p1; ls1 += p2 + p3;
            *(float2*)&sP[(wm + g    )*PP + 8*nt + 2*c] = make_float2(p0, p1);
            *(float2*)&sP[(wm + g + 8)*PP + 8*nt + 2*c] = make_float2(p2, p3);
        }
        ls0 += __shfl_xor_sync(0xffffffffu, ls0, 1);
        ls0 += __shfl_xor_sync(0xffffffffu, ls0, 2);
        ls1 += __shfl_xor_sync(0xffffffffu, ls1, 1);
        ls1 += __shfl_xor_sync(0xffffffffu, ls1, 2);
        l_r[0] = l_r[0] * alpha0 + ls0;
        l_r[1] = l_r[1] * alpha1 + ls1;

        // ---- rescale O ----
#pragma unroll
        for (int nt = 0; nt < 16; nt++) {
            acco[nt][0] *= alpha0; acco[nt][1] *= alpha0;
            acco[nt][2] *= alpha1; acco[nt][3] *= alpha1;
        }
        __syncwarp();   // sP writes visible to all lanes of this warp

        // ---- O += P V : warp tile 16x128, 16 n-frags, k=64 ----
#pragma unroll
        for (int k8 = 0; k8 < 8; k8++) {
            const int kb = k8 * 8;
            unsigned a[4];
            a[0] = uP[(wm + g    )*PP + kb + c    ];
            a[1] = uP[(wm + g + 8)*PP + kb + c    ];
            a[2] = uP[(wm + g    )*PP + kb + c + 4];
            a[3] = uP[(wm + g + 8)*PP + kb + c + 4];
#pragma unroll
            for (int nt = 0; nt < 16; nt++) {
                unsigned b[2];
                b[0] = uV[(kb + c    )*VPS + 8*nt + g];
                b[1] = uV[(kb + c + 4)*VPS + 8*nt + g];
                mma_tf32(acco[nt], a, b);
            }
        }
    }

    // Epilogue: normalize + write [B*S, H]
    const int b = bh >> 4;
    const int h = bh & 15;
    const float inv0 = 1.f / l_r[0];
    const float inv1 = 1.f / l_r[1];
    float* base0 = out + ((size_t)(b*SEQ + q0 + wm + g    ))*HID + h*HD;
    float* base1 = out + ((size_t)(b*SEQ + q0 + wm + g + 8))*HID + h*HD;
#pragma unroll
    for (int nt = 0; nt < 16; nt++) {
        *(float2*)&base0[8*nt + 2*c] = make_float2(acco[nt][0]*inv0, acco[nt][1]*inv0);
        *(float2*)&base1[8*nt + 2*c] = make_float2(acco[nt][2]*inv1, acco[nt][3]*inv1);
    }
}

// ---------------------------------------------------------------------------
// Launch
// ---------------------------------------------------------------------------
extern "C" void kernel_launch(void* const* d_in, const int* in_sizes, int n_in,
                              void* d_out, int out_size)
{
    const float* x  = (const float*)d_in[0];
    const float* Wq = (const float*)d_in[1];
    const float* Wk = (const float*)d_in[2];
    const float* Wv = (const float*)d_in[3];
    const float* Wo = (const float*)d_in[4];

    float *pQ, *pK, *pV, *pAO;
    cudaGetSymbolAddress((void**)&pQ,  g_Q);
    cudaGetSymbolAddress((void**)&pK,  g_K);
    cudaGetSymbolAddress((void**)&pV,  g_V);
    cudaGetSymbolAddress((void**)&pAO, g_AO);

    dim3 gemm_grid(HID / TBN, MTOT / TBM);   // (16, 64)

    gemm_tf32_kernel<<<gemm_grid, 256>>>(x, Wq, pQ, 0);
    gemm_tf32_kernel<<<gemm_grid, 256>>>(x, Wk, pK, 0);
    gemm_tf32_kernel<<<gemm_grid, 256>>>(x, Wv, pV, 0);

    rope_kernel<<<BATCH*NHEAD*SEQ/4, 256>>>(pQ, pK);

    cudaFuncSetAttribute(attn_mma_kernel, cudaFuncAttributeMaxDynamicSharedMemorySize,
                         ATTN_SMEM_BYTES);
    attn_mma_kernel<<<dim3(SEQ/ABR, BATCH*NHEAD), 256, ATTN_SMEM_BYTES>>>(pQ, pK, pV, pAO);

    gemm_tf32_kernel<<<gemm_grid, 256>>>(pAO, Wo, (float*)d_out, 1);
}

// round 5
// speedup vs baseline: 6.0892x; 1.4669x over previous
#include <cuda_runtime.h>
#include <cuda_fp16.h>
#include <math.h>

// Problem constants
#define BATCH 4
#define SEQ   2048
#define HID   2048
#define NHEAD 16
#define HD    128
#define MTOT  (BATCH*SEQ)        // 8192
#define SCALE 0.08838834764831845f   // 1/sqrt(128)

// Scratch buffers
__device__ float  g_Q[(size_t)BATCH*NHEAD*SEQ*HD];   // [b*16+h][s][d] fp32
__device__ float  g_K[(size_t)BATCH*NHEAD*SEQ*HD];
__device__ float  g_V[(size_t)BATCH*NHEAD*SEQ*HD];
__device__ __half g_xh[(size_t)MTOT*HID];            // x fp16; reused as AO fp16
__device__ __half g_wh[4][(size_t)HID*HID];          // weights fp16

// ---------------------------------------------------------------------------
// PTX helpers
// ---------------------------------------------------------------------------
__device__ __forceinline__ unsigned smem_u32(const void* p) {
    unsigned a;
    asm("{ .reg .u64 t; cvta.to.shared.u64 t, %1; cvt.u32.u64 %0, t; }"
        : "=r"(a) : "l"(p));
    return a;
}

__device__ __forceinline__ void cp16(unsigned dst, const void* src) {
    asm volatile("cp.async.cg.shared.global [%0], [%1], 16;\n"
                 :: "r"(dst), "l"(src) : "memory");
}
#define CP_COMMIT() asm volatile("cp.async.commit_group;\n" ::: "memory")
#define CP_WAIT2()  asm volatile("cp.async.wait_group 2;\n" ::: "memory")

__device__ __forceinline__ void ldm_x4(unsigned& r0, unsigned& r1,
                                       unsigned& r2, unsigned& r3, unsigned addr) {
    asm volatile("ldmatrix.sync.aligned.m8n8.x4.shared.b16 {%0,%1,%2,%3}, [%4];"
                 : "=r"(r0), "=r"(r1), "=r"(r2), "=r"(r3) : "r"(addr));
}
__device__ __forceinline__ void ldm_x4_t(unsigned& r0, unsigned& r1,
                                         unsigned& r2, unsigned& r3, unsigned addr) {
    asm volatile("ldmatrix.sync.aligned.m8n8.x4.trans.shared.b16 {%0,%1,%2,%3}, [%4];"
                 : "=r"(r0), "=r"(r1), "=r"(r2), "=r"(r3) : "r"(addr));
}

__device__ __forceinline__ void mma_f16(float (&d)[4], const unsigned (&a)[4],
                                        const unsigned (&b)[2]) {
    asm volatile(
        "mma.sync.aligned.m16n8k16.row.col.f32.f16.f16.f32 "
        "{%0,%1,%2,%3}, {%4,%5,%6,%7}, {%8,%9}, {%0,%1,%2,%3};\n"
        : "+f"(d[0]), "+f"(d[1]), "+f"(d[2]), "+f"(d[3])
        : "r"(a[0]), "r"(a[1]), "r"(a[2]), "r"(a[3]),
          "r"(b[0]), "r"(b[1]));
}

// ---------------------------------------------------------------------------
// fp32 -> fp16 conversion
// ---------------------------------------------------------------------------
__global__ void cvt_kernel(const float* __restrict__ src,
                           __half* __restrict__ dst, int n4)
{
    const int i = blockIdx.x * blockDim.x + threadIdx.x;
    if (i >= n4) return;
    float4 v = ((const float4*)src)[i];
    __half2 h0 = __floats2half2_rn(v.x, v.y);
    __half2 h1 = __floats2half2_rn(v.z, v.w);
    __half2* d = (__half2*)&dst[(size_t)4*i];
    d[0] = h0; d[1] = h1;
}

// ---------------------------------------------------------------------------
// fp16 tensor GEMM (NT): C[m,n] = sum_k A[m,k]*W[n,k], fp32 accumulate.
// 128x128 tile, BK=32 halves, 4-stage cp.async ring, ldmatrix fragments.
// 8 warps (2x4): warp tile 64x32. Smem row stride 40 halves (80B) —
// conflict-free for ldmatrix (starts 0,20,8,28,16,4,24,12 mod 32).
// ---------------------------------------------------------------------------
#define GBK 32
#define GSTR 40                          // halves per smem row
#define GROWB 80                         // bytes per smem row
#define GTILE_B (128*GROWB)              // 10240 bytes per operand tile
#define GSTAGE_B (2*GTILE_B)             // A+B = 20480
#define GSTAGES 4
#define G_SMEM (GSTAGES*GSTAGE_B)        // 81920
#define GNK (HID/GBK)                    // 64

__global__ __launch_bounds__(256)
void gemm_fp16_kernel(const __half* __restrict__ Ah, const __half* __restrict__ Wh,
                      float* __restrict__ out, int qkv_mode)
{
    extern __shared__ __align__(16) char smem[];
    const unsigned sbase = smem_u32(smem);
    const int tid = threadIdx.x;
    const int warp = tid >> 5, lane = tid & 31;
    const int m0 = blockIdx.y * 128;
    const int n0 = blockIdx.x * 128;
    const int wm = (warp >> 2) * 64;
    const int wn = (warp & 3) * 32;
    const int g = lane >> 2, c = lane & 3;

    float acc[4][4][4];
#pragma unroll
    for (int mt = 0; mt < 4; mt++)
#pragma unroll
        for (int nt = 0; nt < 4; nt++)
#pragma unroll
            for (int e = 0; e < 4; e++) acc[mt][nt][e] = 0.f;

    // Load geometry: thread -> (row = tid>>1, half-chunk = (tid&1)*16)
    const int lrow = tid >> 1;
    const int lofs = (tid & 1) << 4;           // halves
    const __half* Ar = Ah + (size_t)(m0 + lrow) * HID + lofs;
    const __half* Wr = Wh + (size_t)(n0 + lrow) * HID + lofs;
    const unsigned sm_off = (unsigned)lrow * GROWB + (unsigned)(tid & 1) * 32;

    auto load_stage = [&](int q) {
        const unsigned s = sbase + (q & 3) * GSTAGE_B;
        const __half* a = Ar + q * GBK;
        const __half* w = Wr + q * GBK;
        cp16(s + sm_off,               a);
        cp16(s + sm_off + 16,          a + 8);
        cp16(s + GTILE_B + sm_off,     w);
        cp16(s + GTILE_B + sm_off + 16, w + 8);
    };

    load_stage(0); CP_COMMIT();
    load_stage(1); CP_COMMIT();
    load_stage(2); CP_COMMIT();

    for (int q = 0; q < GNK; q++) {
        CP_WAIT2();
        __syncthreads();
        if (q + 3 < GNK) load_stage(q + 3);
        CP_COMMIT();                        // possibly empty group: keeps count uniform

        const unsigned sa = sbase + (q & 3) * GSTAGE_B;
        const unsigned sb = sa + GTILE_B;

#pragma unroll
        for (int k16 = 0; k16 < 2; k16++) {
            const unsigned kofs = (unsigned)k16 * 32 + ((unsigned)(lane >> 4) << 4);
            unsigned a[4][4];
#pragma unroll
            for (int mt = 0; mt < 4; mt++) {
                const unsigned addr = sa + (unsigned)(wm + 16*mt + (lane & 15)) * GROWB + kofs;
                ldm_x4(a[mt][0], a[mt][1], a[mt][2], a[mt][3], addr);
            }
            unsigned b[4][2];
#pragma unroll
            for (int nt2 = 0; nt2 < 2; nt2++) {
                const unsigned addr = sb
                    + (unsigned)(wn + 16*nt2 + (lane & 7) + ((lane >> 4) << 3)) * GROWB
                    + (unsigned)k16 * 32 + (unsigned)((lane >> 3) & 1) * 16;
                ldm_x4(b[2*nt2][0], b[2*nt2][1], b[2*nt2+1][0], b[2*nt2+1][1], addr);
            }
#pragma unroll
            for (int mt = 0; mt < 4; mt++)
#pragma unroll
                for (int nt = 0; nt < 4; nt++)
                    mma_f16(acc[mt][nt], a[mt], b[nt]);
        }
    }

    // Epilogue
#pragma unroll
    for (int mt = 0; mt < 4; mt++) {
#pragma unroll
        for (int nt = 0; nt < 4; nt++) {
            const int row = m0 + wm + mt*16 + g;
            const int col = n0 + wn + nt*8 + 2*c;
            float2 lo = make_float2(acc[mt][nt][0], acc[mt][nt][1]);
            float2 hi = make_float2(acc[mt][nt][2], acc[mt][nt][3]);
            if (qkv_mode == 0) {
                const int b = row >> 11;
                const int s = row & (SEQ-1);
                const int h = col >> 7;
                const int d = col & (HD-1);
                float* dst = out + (((size_t)(b*NHEAD + h))*SEQ + s)*HD + d;
                *(float2*)dst = lo;
                *(float2*)(dst + (size_t)8*HD) = hi;
            } else {
                *(float2*)(out + (size_t)row * HID + col) = lo;
                *(float2*)(out + (size_t)(row + 8) * HID + col) = hi;
            }
        }
    }
}

// ---------------------------------------------------------------------------
// RoPE (swapped sin/cos naming, faithful to reference); fp32 in-place
// ---------------------------------------------------------------------------
__global__ void rope_kernel(float* __restrict__ Q, float* __restrict__ Kk)
{
    const int row = blockIdx.x * 4 + (threadIdx.x >> 6);
    const int j   = threadIdx.x & 63;
    const int s   = row & (SEQ - 1);

    const double e = -((double)(2*j) / 128.0) * 9.210340371976184;
    const float inv = (float)exp(e);
    const float ang = (float)s * inv;
    float sn, cs;
    sincosf(ang, &sn, &cs);

    const size_t base = (size_t)row * HD;
    float q1 = Q[base + j], q2 = Q[base + j + 64];
    Q[base + j]      = q1 * sn - q2 * cs;
    Q[base + j + 64] = q1 * cs + q2 * sn;

    float k1 = Kk[base + j], k2 = Kk[base + j + 64];
    Kk[base + j]      = k1 * sn - k2 * cs;
    Kk[base + j + 64] = k1 * cs + k2 * sn;
}

// ---------------------------------------------------------------------------
// Causal flash attention on fp16 mma.sync (fp32 accumulate, fp32 softmax).
// BR=128, BC=64, 256 threads = 8 warps; warp w owns rows 16w..16w+15.
// Q fragments hoisted to registers; sP aliases the dead sQ region.
// Output written as fp16 directly (input format of the O-projection GEMM).
// smem strides (halves): Q/K/V 136 (272B), P 72 (144B) — ldmatrix conflict-free.
// ---------------------------------------------------------------------------
#define ABR 128
#define ABC 64
#define AQSTR 136
#define APSTR 72
#define SQ_BYTES (ABR*AQSTR*2)          // 34816 (>= ABR*APSTR*2 = 18432)
#define SK_BYTES (ABC*AQSTR*2)          // 17408
#define ATTN_SMEM (SQ_BYTES + 2*SK_BYTES)

__global__ __launch_bounds__(256, 1)
void attn_f16_kernel(const float* __restrict__ Q, const float* __restrict__ K,
                     const float* __restrict__ V, __half* __restrict__ out)
{
    extern __shared__ __align__(16) char smem[];
    __half* sQ = (__half*)smem;                       // ABR x AQSTR (dead after frag load)
    __half* sK = (__half*)(smem + SQ_BYTES);          // ABC x AQSTR
    __half* sV = (__half*)(smem + SQ_BYTES + SK_BYTES);
    __half* sP = (__half*)smem;                       // aliases sQ: ABR x APSTR
    const unsigned uQ = smem_u32(smem);
    const unsigned uK = uQ + SQ_BYTES;
    const unsigned uV = uK + SK_BYTES;
    const unsigned uP = uQ;

    const int bh = blockIdx.y;
    const int q0 = blockIdx.x * ABR;
    const int tid = threadIdx.x;
    const int warp = tid >> 5, lane = tid & 31;
    const int g = lane >> 2, c = lane & 3;
    const int wm = warp * 16;

    const float* Qb = Q + (size_t)bh * SEQ * HD;
    const float* Kb = K + (size_t)bh * SEQ * HD;
    const float* Vb = V + (size_t)bh * SEQ * HD;

    // Fill sQ (128x128 f32 -> f16)
    for (int i = tid; i < ABR*HD/4; i += 256) {
        const int r = i >> 5;
        const int c4 = (i & 31) << 2;
        float4 v = *(const float4*)&Qb[(size_t)(q0 + r)*HD + c4];
        __half2* d = (__half2*)&sQ[r*AQSTR + c4];
        d[0] = __floats2half2_rn(v.x, v.y);
        d[1] = __floats2half2_rn(v.z, v.w);
    }
    __syncthreads();

    // Hoist Q fragments: 8 k16-steps x 4 regs
    unsigned qa[8][4];
#pragma unroll
    for (int k16 = 0; k16 < 8; k16++) {
        const unsigned addr = uQ + (unsigned)(wm + (lane & 15)) * (AQSTR*2)
                            + (unsigned)k16 * 32 + ((unsigned)(lane >> 4) << 4);
        ldm_x4(qa[k16][0], qa[k16][1], qa[k16][2], qa[k16][3], addr);
    }

    float m_r[2] = { -1e30f, -1e30f };
    float l_r[2] = { 0.f, 0.f };
    float acco[16][4];
#pragma unroll
    for (int nt = 0; nt < 16; nt++)
#pragma unroll
        for (int e = 0; e < 4; e++) acco[nt][e] = 0.f;

    const int qi0 = q0 + wm + g;
    const int qi1 = qi0 + 8;
    const int ktmax = q0/ABC + 1;

    for (int kt = 0; kt <= ktmax; kt++) {
        const int k0 = kt * ABC;
        __syncthreads();   // previous tile's sK/sV reads (and sP use) done

        // Fill sK, sV (64x128 f32 -> f16)
        for (int i = tid; i < ABC*HD/4; i += 256) {
            const int r = i >> 5;
            const int c4 = (i & 31) << 2;
            float4 kv = *(const float4*)&Kb[(size_t)(k0 + r)*HD + c4];
            __half2* dk = (__half2*)&sK[r*AQSTR + c4];
            dk[0] = __floats2half2_rn(kv.x, kv.y);
            dk[1] = __floats2half2_rn(kv.z, kv.w);
            float4 vv = *(const float4*)&Vb[(size_t)(k0 + r)*HD + c4];
            __half2* dv = (__half2*)&sV[r*AQSTR + c4];
            dv[0] = __floats2half2_rn(vv.x, vv.y);
            dv[1] = __floats2half2_rn(vv.z, vv.w);
        }
        __syncthreads();

        if (k0 > q0 + wm + 15) continue;   // warp tile fully masked

        // ---- S = Q K^T : 8 k16 steps, 8 n-frags ----
        float accs[8][4];
#pragma unroll
        for (int nt = 0; nt < 8; nt++)
#pragma unroll
            for (int e = 0; e < 4; e++) accs[nt][e] = 0.f;

#pragma unroll
        for (int k16 = 0; k16 < 8; k16++) {
            unsigned b[8][2];
#pragma unroll
            for (int nt2 = 0; nt2 < 4; nt2++) {
                const unsigned addr = uK
                    + (unsigned)(16*nt2 + (lane & 7) + ((lane >> 4) << 3)) * (AQSTR*2)
                    + (unsigned)k16 * 32 + (unsigned)((lane >> 3) & 1) * 16;
                ldm_x4(b[2*nt2][0], b[2*nt2][1], b[2*nt2+1][0], b[2*nt2+1][1], addr);
            }
#pragma unroll
            for (int nt = 0; nt < 8; nt++)
                mma_f16(accs[nt], qa[k16], b[nt]);
        }

        // ---- scale + causal mask + row max ----
        float mx0 = m_r[0], mx1 = m_r[1];
#pragma unroll
        for (int nt = 0; nt < 8; nt++) {
            const int colb = k0 + 8*nt + 2*c;
            float v0 = accs[nt][0] * SCALE; if (colb     > qi0) v0 = -1e30f;
            float v1 = accs[nt][1] * SCALE; if (colb + 1 > qi0) v1 = -1e30f;
            float v2 = accs[nt][2] * SCALE; if (colb     > qi1) v2 = -1e30f;
            float v3 = accs[nt][3] * SCALE; if (colb + 1 > qi1) v3 = -1e30f;
            accs[nt][0] = v0; accs[nt][1] = v1; accs[nt][2] = v2; accs[nt][3] = v3;
            mx0 = fmaxf(mx0, fmaxf(v0, v1));
            mx1 = fmaxf(mx1, fmaxf(v2, v3));
        }
        mx0 = fmaxf(mx0, __shfl_xor_sync(0xffffffffu, mx0, 1));
        mx0 = fmaxf(mx0, __shfl_xor_sync(0xffffffffu, mx0, 2));
        mx1 = fmaxf(mx1, __shfl_xor_sync(0xffffffffu, mx1, 1));
        mx1 = fmaxf(mx1, __shfl_xor_sync(0xffffffffu, mx1, 2));

        const float alpha0 = __expf(m_r[0] - mx0);
        const float alpha1 = __expf(m_r[1] - mx1);
        m_r[0] = mx0; m_r[1] = mx1;

        // ---- exp; round P to fp16; l sums the ROUNDED p (normalization cancels) ----
        float ls0 = 0.f, ls1 = 0.f;
#pragma unroll
        for (int nt = 0; nt < 8; nt++) {
            __half2 p01 = __floats2half2_rn(__expf(accs[nt][0] - mx0),
                                            __expf(accs[nt][1] - mx0));
            __half2 p23 = __floats2half2_rn(__expf(accs[nt][2] - mx1),
                                            __expf(accs[nt][3] - mx1));
            float2 f01 = __half22float2(p01);
            float2 f23 = __half22float2(p23);
            ls0 += f01.x + f01.y;
            ls1 += f23.x + f23.y;
            *(__half2*)&sP[(wm + g    )*APSTR + 8*nt + 2*c] = p01;
            *(__half2*)&sP[(wm + g + 8)*APSTR + 8*nt + 2*c] = p23;
        }
        ls0 += __shfl_xor_sync(0xffffffffu, ls0, 1);
        ls0 += __shfl_xor_sync(0xffffffffu, ls0, 2);
        ls1 += __shfl_xor_sync(0xffffffffu, ls1, 1);
        ls1 += __shfl_xor_sync(0xffffffffu, ls1, 2);
        l_r[0] = l_r[0] * alpha0 + ls0;
        l_r[1] = l_r[1] * alpha1 + ls1;

#pragma unroll
        for (int nt = 0; nt < 16; nt++) {
            acco[nt][0] *= alpha0; acco[nt][1] *= alpha0;
            acco[nt][2] *= alpha1; acco[nt][3] *= alpha1;
        }
        __syncwarp();   // sP rows are warp-private; writes visible within warp

        // ---- O += P V : 4 k16 steps, 16 n-frags; V fragments via ldmatrix.trans ----
#pragma unroll
        for (int k16 = 0; k16 < 4; k16++) {
            unsigned a[4];
            {
                const unsigned addr = uP + (unsigned)(wm + (lane & 15)) * (APSTR*2)
                                    + (unsigned)k16 * 32 + ((unsigned)(lane >> 4) << 4);
                ldm_x4(a[0], a[1], a[2], a[3], addr);
            }
#pragma unroll
            for (int nt2 = 0; nt2 < 8; nt2++) {
                unsigned b[2][2];
                const unsigned addr = uV
                    + (unsigned)(k16*16 + (lane & 7) + (((lane >> 3) & 1) << 3)) * (AQSTR*2)
                    + (unsigned)(2*nt2 + (lane >> 4)) * 16;
                ldm_x4_t(b[0][0], b[0][1], b[1][0], b[1][1], addr);
                mma_f16(acco[2*nt2],     a, b[0]);
                mma_f16(acco[2*nt2 + 1], a, b[1]);
            }
        }
    }

    // Epilogue: normalize, write fp16 [B*S, H]
    const int b = bh >> 4;
    const int h = bh & 15;
    const float inv0 = 1.f / l_r[0];
    const float inv1 = 1.f / l_r[1];
    __half* base0 = out + ((size_t)(b*SEQ + q0 + wm + g    ))*HID + h*HD;
    __half* base1 = out + ((size_t)(b*SEQ + q0 + wm + g + 8))*HID + h*HD;
#pragma unroll
    for (int nt = 0; nt < 16; nt++) {
        *(__half2*)&base0[8*nt + 2*c] = __floats2half2_rn(acco[nt][0]*inv0, acco[nt][1]*inv0);
        *(__half2*)&base1[8*nt + 2*c] = __floats2half2_rn(acco[nt][2]*inv1, acco[nt][3]*inv1);
    }
}

// ---------------------------------------------------------------------------
// Launch
// ---------------------------------------------------------------------------
extern "C" void kernel_launch(void* const* d_in, const int* in_sizes, int n_in,
                              void* d_out, int out_size)
{
    const float* x  = (const float*)d_in[0];
    const float* Ws[4] = {(const float*)d_in[1], (const float*)d_in[2],
                          (const float*)d_in[3], (const float*)d_in[4]};

    float *pQ, *pK, *pV;
    __half *xh, *wh;
    cudaGetSymbolAddress((void**)&pQ, g_Q);
    cudaGetSymbolAddress((void**)&pK, g_K);
    cudaGetSymbolAddress((void**)&pV, g_V);
    cudaGetSymbolAddress((void**)&xh, g_xh);
    cudaGetSymbolAddress((void**)&wh, g_wh);

    const int nx4 = MTOT*HID/4;
    const int nw4 = HID*HID/4;
    const size_t wstride = (size_t)HID*HID;

    cvt_kernel<<<nx4/256, 256>>>(x, xh, nx4);
    for (int i = 0; i < 4; i++)
        cvt_kernel<<<nw4/256, 256>>>(Ws[i], wh + i*wstride, nw4);

    cudaFuncSetAttribute(gemm_fp16_kernel, cudaFuncAttributeMaxDynamicSharedMemorySize,
                         G_SMEM);
    dim3 gg(HID/128, MTOT/128);   // (16, 64)

    gemm_fp16_kernel<<<gg, 256, G_SMEM>>>(xh, wh + 0*wstride, pQ, 0);
    gemm_fp16_kernel<<<gg, 256, G_SMEM>>>(xh, wh + 1*wstride, pK, 0);
    gemm_fp16_kernel<<<gg, 256, G_SMEM>>>(xh, wh + 2*wstride, pV, 0);

    rope_kernel<<<BATCH*NHEAD*SEQ/4, 256>>>(pQ, pK);

    cudaFuncSetAttribute(attn_f16_kernel, cudaFuncAttributeMaxDynamicSharedMemorySize,
                         ATTN_SMEM);
    // attn writes its fp16 output into xh (x no longer needed)
    attn_f16_kernel<<<dim3(SEQ/ABR, BATCH*NHEAD), 256, ATTN_SMEM>>>(pQ, pK, pV, xh);

    gemm_fp16_kernel<<<gg, 256, G_SMEM>>>(xh, wh + 3*wstride, (float*)d_out, 1);
}

// round 6
// speedup vs baseline: 7.1540x; 1.1749x over previous
#include <cuda_runtime.h>
#include <cuda_fp16.h>
#include <math.h>

// Problem constants
#define BATCH 4
#define SEQ   2048
#define HID   2048
#define NHEAD 16
#define HD    128
#define MTOT  (BATCH*SEQ)        // 8192
#define SCALE 0.08838834764831845f   // 1/sqrt(128)

// Scratch buffers
__device__ float  g_Q[(size_t)BATCH*NHEAD*SEQ*HD];   // fp32 [bh][s][d] (pre-rope)
__device__ float  g_K[(size_t)BATCH*NHEAD*SEQ*HD];
__device__ __half g_Qh[(size_t)BATCH*NHEAD*SEQ*HD];  // fp16 [bh][s][d] (post-rope)
__device__ __half g_Kh[(size_t)BATCH*NHEAD*SEQ*HD];
__device__ __half g_Vh[(size_t)BATCH*NHEAD*SEQ*HD];  // fp16 [bh][s][d]
__device__ __half g_xh[(size_t)MTOT*HID];            // x fp16; reused as AO fp16
__device__ __half g_wh[4][(size_t)HID*HID];          // weights fp16

// ---------------------------------------------------------------------------
// PTX helpers
// ---------------------------------------------------------------------------
__device__ __forceinline__ unsigned smem_u32(const void* p) {
    unsigned a;
    asm("{ .reg .u64 t; cvta.to.shared.u64 t, %1; cvt.u32.u64 %0, t; }"
        : "=r"(a) : "l"(p));
    return a;
}

__device__ __forceinline__ void cp16(unsigned dst, const void* src) {
    asm volatile("cp.async.cg.shared.global [%0], [%1], 16;\n"
                 :: "r"(dst), "l"(src) : "memory");
}
#define CP_COMMIT() asm volatile("cp.async.commit_group;\n" ::: "memory")
#define CP_WAIT2()  asm volatile("cp.async.wait_group 2;\n" ::: "memory")
#define CP_WAIT1()  asm volatile("cp.async.wait_group 1;\n" ::: "memory")
#define CP_WAIT0()  asm volatile("cp.async.wait_group 0;\n" ::: "memory")

__device__ __forceinline__ void ldm_x4(unsigned& r0, unsigned& r1,
                                       unsigned& r2, unsigned& r3, unsigned addr) {
    asm volatile("ldmatrix.sync.aligned.m8n8.x4.shared.b16 {%0,%1,%2,%3}, [%4];"
                 : "=r"(r0), "=r"(r1), "=r"(r2), "=r"(r3) : "r"(addr));
}
__device__ __forceinline__ void ldm_x4_t(unsigned& r0, unsigned& r1,
                                         unsigned& r2, unsigned& r3, unsigned addr) {
    asm volatile("ldmatrix.sync.aligned.m8n8.x4.trans.shared.b16 {%0,%1,%2,%3}, [%4];"
                 : "=r"(r0), "=r"(r1), "=r"(r2), "=r"(r3) : "r"(addr));
}

__device__ __forceinline__ void mma_f16(float (&d)[4], const unsigned (&a)[4],
                                        const unsigned (&b)[2]) {
    asm volatile(
        "mma.sync.aligned.m16n8k16.row.col.f32.f16.f16.f32 "
        "{%0,%1,%2,%3}, {%4,%5,%6,%7}, {%8,%9}, {%0,%1,%2,%3};\n"
        : "+f"(d[0]), "+f"(d[1]), "+f"(d[2]), "+f"(d[3])
        : "r"(a[0]), "r"(a[1]), "r"(a[2]), "r"(a[3]),
          "r"(b[0]), "r"(b[1]));
}

// ---------------------------------------------------------------------------
// fp32 -> fp16 conversion
// ---------------------------------------------------------------------------
__global__ void cvt_kernel(const float* __restrict__ src,
                           __half* __restrict__ dst, int n4)
{
    const int i = blockIdx.x * blockDim.x + threadIdx.x;
    if (i >= n4) return;
    float4 v = ((const float4*)src)[i];
    __half2 h0 = __floats2half2_rn(v.x, v.y);
    __half2 h1 = __floats2half2_rn(v.z, v.w);
    __half2* d = (__half2*)&dst[(size_t)4*i];
    d[0] = h0; d[1] = h1;
}

// ---------------------------------------------------------------------------
// fp16 tensor GEMM (NT): C[m,n] = sum_k A[m,k]*W[n,k], fp32 accumulate.
// qkv_mode: 0 = fp32 scatter [bh][s][d];  1 = fp32 row-major [M,N];
//           2 = fp16 scatter [bh][s][d]
// ---------------------------------------------------------------------------
#define GBK 32
#define GROWB 80                         // bytes per smem row (40 halves)
#define GTILE_B (128*GROWB)              // 10240
#define GSTAGE_B (2*GTILE_B)             // 20480
#define G_SMEM (4*GSTAGE_B)              // 81920
#define GNK (HID/GBK)                    // 64

__global__ __launch_bounds__(256)
void gemm_fp16_kernel(const __half* __restrict__ Ah, const __half* __restrict__ Wh,
                      void* __restrict__ outv, int qkv_mode)
{
    extern __shared__ __align__(16) char smem[];
    const unsigned sbase = smem_u32(smem);
    const int tid = threadIdx.x;
    const int warp = tid >> 5, lane = tid & 31;
    const int m0 = blockIdx.y * 128;
    const int n0 = blockIdx.x * 128;
    const int wm = (warp >> 2) * 64;
    const int wn = (warp & 3) * 32;
    const int g = lane >> 2, c = lane & 3;

    float acc[4][4][4];
#pragma unroll
    for (int mt = 0; mt < 4; mt++)
#pragma unroll
        for (int nt = 0; nt < 4; nt++)
#pragma unroll
            for (int e = 0; e < 4; e++) acc[mt][nt][e] = 0.f;

    const int lrow = tid >> 1;
    const int lofs = (tid & 1) << 4;
    const __half* Ar = Ah + (size_t)(m0 + lrow) * HID + lofs;
    const __half* Wr = Wh + (size_t)(n0 + lrow) * HID + lofs;
    const unsigned sm_off = (unsigned)lrow * GROWB + (unsigned)(tid & 1) * 32;

    auto load_stage = [&](int q) {
        const unsigned s = sbase + (q & 3) * GSTAGE_B;
        const __half* a = Ar + q * GBK;
        const __half* w = Wr + q * GBK;
        cp16(s + sm_off,                a);
        cp16(s + sm_off + 16,           a + 8);
        cp16(s + GTILE_B + sm_off,      w);
        cp16(s + GTILE_B + sm_off + 16, w + 8);
    };

    load_stage(0); CP_COMMIT();
    load_stage(1); CP_COMMIT();
    load_stage(2); CP_COMMIT();

    for (int q = 0; q < GNK; q++) {
        CP_WAIT2();
        __syncthreads();
        if (q + 3 < GNK) load_stage(q + 3);
        CP_COMMIT();

        const unsigned sa = sbase + (q & 3) * GSTAGE_B;
        const unsigned sb = sa + GTILE_B;

#pragma unroll
        for (int k16 = 0; k16 < 2; k16++) {
            const unsigned kofs = (unsigned)k16 * 32 + ((unsigned)(lane >> 4) << 4);
            unsigned a[4][4];
#pragma unroll
            for (int mt = 0; mt < 4; mt++) {
                const unsigned addr = sa + (unsigned)(wm + 16*mt + (lane & 15)) * GROWB + kofs;
                ldm_x4(a[mt][0], a[mt][1], a[mt][2], a[mt][3], addr);
            }
            unsigned b[4][2];
#pragma unroll
            for (int nt2 = 0; nt2 < 2; nt2++) {
                const unsigned addr = sb
                    + (unsigned)(wn + 16*nt2 + (lane & 7) + ((lane >> 4) << 3)) * GROWB
                    + (unsigned)k16 * 32 + (unsigned)((lane >> 3) & 1) * 16;
                ldm_x4(b[2*nt2][0], b[2*nt2][1], b[2*nt2+1][0], b[2*nt2+1][1], addr);
            }
#pragma unroll
            for (int mt = 0; mt < 4; mt++)
#pragma unroll
                for (int nt = 0; nt < 4; nt++)
                    mma_f16(acc[mt][nt], a[mt], b[nt]);
        }
    }

    // Epilogue
#pragma unroll
    for (int mt = 0; mt < 4; mt++) {
#pragma unroll
        for (int nt = 0; nt < 4; nt++) {
            const int row = m0 + wm + mt*16 + g;
            const int col = n0 + wn + nt*8 + 2*c;
            float2 lo = make_float2(acc[mt][nt][0], acc[mt][nt][1]);
            float2 hi = make_float2(acc[mt][nt][2], acc[mt][nt][3]);
            if (qkv_mode == 0) {
                float* out = (float*)outv;
                const int b = row >> 11;
                const int s = row & (SEQ-1);
                const int h = col >> 7;
                const int d = col & (HD-1);
                float* dst = out + (((size_t)(b*NHEAD + h))*SEQ + s)*HD + d;
                *(float2*)dst = lo;
                *(float2*)(dst + (size_t)8*HD) = hi;
            } else if (qkv_mode == 1) {
                float* out = (float*)outv;
                *(float2*)(out + (size_t)row * HID + col) = lo;
                *(float2*)(out + (size_t)(row + 8) * HID + col) = hi;
            } else {
                __half* out = (__half*)outv;
                const int b = row >> 11;
                const int s = row & (SEQ-1);
                const int h = col >> 7;
                const int d = col & (HD-1);
                __half* dst = out + (((size_t)(b*NHEAD + h))*SEQ + s)*HD + d;
                *(__half2*)dst = __floats2half2_rn(lo.x, lo.y);
                *(__half2*)(dst + (size_t)8*HD) = __floats2half2_rn(hi.x, hi.y);
            }
        }
    }
}

// ---------------------------------------------------------------------------
// RoPE (swapped sin/cos naming, faithful to reference): fp32 in -> fp16 out
// ---------------------------------------------------------------------------
__global__ void rope_f16_kernel(const float* __restrict__ Q, const float* __restrict__ Kk,
                                __half* __restrict__ Qh, __half* __restrict__ Kh)
{
    const int row = blockIdx.x * 4 + (threadIdx.x >> 6);
    const int j   = threadIdx.x & 63;
    const int s   = row & (SEQ - 1);

    const double e = -((double)(2*j) / 128.0) * 9.210340371976184;
    const float inv = (float)exp(e);
    const float ang = (float)s * inv;
    float sn, cs;
    sincosf(ang, &sn, &cs);

    const size_t base = (size_t)row * HD;
    float q1 = Q[base + j], q2 = Q[base + j + 64];
    Qh[base + j]      = __float2half(q1 * sn - q2 * cs);
    Qh[base + j + 64] = __float2half(q1 * cs + q2 * sn);

    float k1 = Kk[base + j], k2 = Kk[base + j + 64];
    Kh[base + j]      = __float2half(k1 * sn - k2 * cs);
    Kh[base + j + 64] = __float2half(k1 * cs + k2 * sn);
}

// ---------------------------------------------------------------------------
// Causal flash attention, fp16 mma + cp.async double-buffered K/V.
// BR=128, BC=64, 256 threads = 8 warps; warp w owns rows 16w..16w+15.
// Per iter: wait_group 0 -> syncthreads -> issue tile kt+1 -> compute kt.
// sP aliases the dead sQ region (first loop barrier orders hoist vs sP).
// ---------------------------------------------------------------------------
#define ABR 128
#define ABC 64
#define AQSTR 136                       // halves; 272B row stride (16B-aligned)
#define APSTR 72
#define SQ_BYTES (ABR*AQSTR*2)          // 34816
#define SK_BYTES (ABC*AQSTR*2)          // 17408
#define KV_STAGE (2*SK_BYTES)           // 34816
#define ATTN_SMEM (SQ_BYTES + 2*KV_STAGE)   // 104448

__global__ __launch_bounds__(256, 1)
void attn_f16_kernel(const __half* __restrict__ Qh, const __half* __restrict__ Kh,
                     const __half* __restrict__ Vh, __half* __restrict__ out)
{
    extern __shared__ __align__(16) char smem[];
    __half* sP = (__half*)smem;                  // aliases dead sQ
    const unsigned uQ = smem_u32(smem);
    const unsigned uKV = uQ + SQ_BYTES;
    const unsigned uP = uQ;

    const int bh = blockIdx.y;
    const int q0 = blockIdx.x * ABR;
    const int tid = threadIdx.x;
    const int warp = tid >> 5, lane = tid & 31;
    const int g = lane >> 2, c = lane & 3;
    const int wm = warp * 16;

    const __half* Qb = Qh + (size_t)bh * SEQ * HD;
    const __half* Kb = Kh + (size_t)bh * SEQ * HD;
    const __half* Vb = Vh + (size_t)bh * SEQ * HD;

    auto load_kv = [&](int kt, int stage) {
        const int k0 = kt * ABC;
        const unsigned s = uKV + stage * KV_STAGE;
#pragma unroll
        for (int i = 0; i < 4; i++) {
            const int idx = tid + 256*i;         // 0..1023
            const int r = idx >> 4, ch = idx & 15;
            const unsigned so = (unsigned)r * (AQSTR*2) + (unsigned)ch * 16;
            cp16(s + so,            Kb + (size_t)(k0 + r)*HD + ch*8);
            cp16(s + SK_BYTES + so, Vb + (size_t)(k0 + r)*HD + ch*8);
        }
    };

    // Prologue: async Q tile, then KV tile 0
#pragma unroll
    for (int i = 0; i < 8; i++) {
        const int idx = tid + 256*i;             // 0..2047
        const int r = idx >> 4, ch = idx & 15;
        cp16(uQ + (unsigned)r*(AQSTR*2) + (unsigned)ch*16,
             Qb + (size_t)(q0 + r)*HD + ch*8);
    }
    CP_COMMIT();
    load_kv(0, 0);
    CP_COMMIT();
    CP_WAIT1();                 // Q group complete
    __syncthreads();

    // Hoist Q fragments; sQ is dead afterwards
    unsigned qa[8][4];
#pragma unroll
    for (int k16 = 0; k16 < 8; k16++) {
        const unsigned addr = uQ + (unsigned)(wm + (lane & 15)) * (AQSTR*2)
                            + (unsigned)k16 * 32 + ((unsigned)(lane >> 4) << 4);
        ldm_x4(qa[k16][0], qa[k16][1], qa[k16][2], qa[k16][3], addr);
    }

    float m_r[2] = { -1e30f, -1e30f };
    float l_r[2] = { 0.f, 0.f };
    float acco[16][4];
#pragma unroll
    for (int nt = 0; nt < 16; nt++)
#pragma unroll
        for (int e = 0; e < 4; e++) acco[nt][e] = 0.f;

    const int qi0 = q0 + wm + g;
    const int qi1 = qi0 + 8;
    const int ktmax = q0/ABC + 1;

    for (int kt = 0; kt <= ktmax; kt++) {
        const int k0 = kt * ABC;
        CP_WAIT0();             // tile kt resident
        __syncthreads();        // ...and all threads done reading stage (kt+1)&1
        if (kt + 1 <= ktmax) load_kv(kt + 1, (kt + 1) & 1);
        CP_COMMIT();

        const unsigned uK = uKV + (kt & 1) * KV_STAGE;
        const unsigned uV = uK + SK_BYTES;

        if (k0 > q0 + wm + 15) continue;   // warp tile fully masked

        // ---- S = Q K^T ----
        float accs[8][4];
#pragma unroll
        for (int nt = 0; nt < 8; nt++)
#pragma unroll
            for (int e = 0; e < 4; e++) accs[nt][e] = 0.f;

#pragma unroll
        for (int k16 = 0; k16 < 8; k16++) {
            unsigned b[8][2];
#pragma unroll
            for (int nt2 = 0; nt2 < 4; nt2++) {
                const unsigned addr = uK
                    + (unsigned)(16*nt2 + (lane & 7) + ((lane >> 4) << 3)) * (AQSTR*2)
                    + (unsigned)k16 * 32 + (unsigned)((lane >> 3) & 1) * 16;
                ldm_x4(b[2*nt2][0], b[2*nt2][1], b[2*nt2+1][0], b[2*nt2+1][1], addr);
            }
#pragma unroll
            for (int nt = 0; nt < 8; nt++)
                mma_f16(accs[nt], qa[k16], b[nt]);
        }

        // ---- scale + causal mask + row max ----
        float mx0 = m_r[0], mx1 = m_r[1];
#pragma unroll
        for (int nt = 0; nt < 8; nt++) {
            const int colb = k0 + 8*nt + 2*c;
            float v0 = accs[nt][0] * SCALE; if (colb     > qi0) v0 = -1e30f;
            float v1 = accs[nt][1] * SCALE; if (colb + 1 > qi0) v1 = -1e30f;
            float v2 = accs[nt][2] * SCALE; if (colb     > qi1) v2 = -1e30f;
            float v3 = accs[nt][3] * SCALE; if (colb + 1 > qi1) v3 = -1e30f;
            accs[nt][0] = v0; accs[nt][1] = v1; accs[nt][2] = v2; accs[nt][3] = v3;
            mx0 = fmaxf(mx0, fmaxf(v0, v1));
            mx1 = fmaxf(mx1, fmaxf(v2, v3));
        }
        mx0 = fmaxf(mx0, __shfl_xor_sync(0xffffffffu, mx0, 1));
        mx0 = fmaxf(mx0, __shfl_xor_sync(0xffffffffu, mx0, 2));
        mx1 = fmaxf(mx1, __shfl_xor_sync(0xffffffffu, mx1, 1));
        mx1 = fmaxf(mx1, __shfl_xor_sync(0xffffffffu, mx1, 2));

        const float alpha0 = __expf(m_r[0] - mx0);
        const float alpha1 = __expf(m_r[1] - mx1);
        m_r[0] = mx0; m_r[1] = mx1;

        // ---- exp; round P to fp16; l sums the ROUNDED p ----
        float ls0 = 0.f, ls1 = 0.f;
#pragma unroll
        for (int nt = 0; nt < 8; nt++) {
            __half2 p01 = __floats2half2_rn(__expf(accs[nt][0] - mx0),
                                            __expf(accs[nt][1] - mx0));
            __half2 p23 = __floats2half2_rn(__expf(accs[nt][2] - mx1),
                                            __expf(accs[nt][3] - mx1));
            float2 f01 = __half22float2(p01);
            float2 f23 = __half22float2(p23);
            ls0 += f01.x + f01.y;
            ls1 += f23.x + f23.y;
            *(__half2*)&sP[(wm + g    )*APSTR + 8*nt + 2*c] = p01;
            *(__half2*)&sP[(wm + g + 8)*APSTR + 8*nt + 2*c] = p23;
        }
        ls0 += __shfl_xor_sync(0xffffffffu, ls0, 1);
        ls0 += __shfl_xor_sync(0xffffffffu, ls0, 2);
        ls1 += __shfl_xor_sync(0xffffffffu, ls1, 1);
        ls1 += __shfl_xor_sync(0xffffffffu, ls1, 2);
        l_r[0] = l_r[0] * alpha0 + ls0;
        l_r[1] = l_r[1] * alpha1 + ls1;

#pragma unroll
        for (int nt = 0; nt < 16; nt++) {
            acco[nt][0] *= alpha0; acco[nt][1] *= alpha0;
            acco[nt][2] *= alpha1; acco[nt][3] *= alpha1;
        }
        __syncwarp();   // sP rows are warp-private

        // ---- O += P V ----
#pragma unroll
        for (int k16 = 0; k16 < 4; k16++) {
            unsigned a[4];
            {
                const unsigned addr = uP + (unsigned)(wm + (lane & 15)) * (APSTR*2)
                                    + (unsigned)k16 * 32 + ((unsigned)(lane >> 4) << 4);
                ldm_x4(a[0], a[1], a[2], a[3], addr);
            }
#pragma unroll
            for (int nt2 = 0; nt2 < 8; nt2++) {
                unsigned b[2][2];
                const unsigned addr = uV
                    + (unsigned)(k16*16 + (lane & 7) + (((lane >> 3) & 1) << 3)) * (AQSTR*2)
                    + (unsigned)(2*nt2 + (lane >> 4)) * 16;
                ldm_x4_t(b[0][0], b[0][1], b[1][0], b[1][1], addr);
                mma_f16(acco[2*nt2],     a, b[0]);
                mma_f16(acco[2*nt2 + 1], a, b[1]);
            }
        }
    }

    // Epilogue: normalize, write fp16 [B*S, H]
    const int b = bh >> 4;
    const int h = bh & 15;
    const float inv0 = 1.f / l_r[0];
    const float inv1 = 1.f / l_r[1];
    __half* base0 = out + ((size_t)(b*SEQ + q0 + wm + g    ))*HID + h*HD;
    __half* base1 = out + ((size_t)(b*SEQ + q0 + wm + g + 8))*HID + h*HD;
#pragma unroll
    for (int nt = 0; nt < 16; nt++) {
        *(__half2*)&base0[8*nt + 2*c] = __floats2half2_rn(acco[nt][0]*inv0, acco[nt][1]*inv0);
        *(__half2*)&base1[8*nt + 2*c] = __floats2half2_rn(acco[nt][2]*inv1, acco[nt][3]*inv1);
    }
}

// ---------------------------------------------------------------------------
// Launch
// ---------------------------------------------------------------------------
extern "C" void kernel_launch(void* const* d_in, const int* in_sizes, int n_in,
                              void* d_out, int out_size)
{
    const float* x  = (const float*)d_in[0];
    const float* Ws[4] = {(const float*)d_in[1], (const float*)d_in[2],
                          (const float*)d_in[3], (const float*)d_in[4]};

    float *pQ, *pK;
    __half *qh, *kh, *vh, *xh, *wh;
    cudaGetSymbolAddress((void**)&pQ, g_Q);
    cudaGetSymbolAddress((void**)&pK, g_K);
    cudaGetSymbolAddress((void**)&qh, g_Qh);
    cudaGetSymbolAddress((void**)&kh, g_Kh);
    cudaGetSymbolAddress((void**)&vh, g_Vh);
    cudaGetSymbolAddress((void**)&xh, g_xh);
    cudaGetSymbolAddress((void**)&wh, g_wh);

    const int nx4 = MTOT*HID/4;
    const int nw4 = HID*HID/4;
    const size_t wstride = (size_t)HID*HID;

    cvt_kernel<<<nx4/256, 256>>>(x, xh, nx4);
    for (int i = 0; i < 4; i++)
        cvt_kernel<<<nw4/256, 256>>>(Ws[i], wh + i*wstride, nw4);

    cudaFuncSetAttribute(gemm_fp16_kernel, cudaFuncAttributeMaxDynamicSharedMemorySize,
                         G_SMEM);
    dim3 gg(HID/128, MTOT/128);   // (16, 64)

    gemm_fp16_kernel<<<gg, 256, G_SMEM>>>(xh, wh + 0*wstride, pQ, 0);   // Q fp32
    gemm_fp16_kernel<<<gg, 256, G_SMEM>>>(xh, wh + 1*wstride, pK, 0);   // K fp32
    gemm_fp16_kernel<<<gg, 256, G_SMEM>>>(xh, wh + 2*wstride, vh, 2);   // V fp16

    rope_f16_kernel<<<BATCH*NHEAD*SEQ/4, 256>>>(pQ, pK, qh, kh);

    cudaFuncSetAttribute(attn_f16_kernel, cudaFuncAttributeMaxDynamicSharedMemorySize,
                         ATTN_SMEM);
    // attn writes fp16 output into xh (x no longer needed)
    attn_f16_kernel<<<dim3(SEQ/ABR, BATCH*NHEAD), 256, ATTN_SMEM>>>(qh, kh, vh, xh);

    gemm_fp16_kernel<<<gg, 256, G_SMEM>>>(xh, wh + 3*wstride, (float*)d_out, 1);
}